// round 3
// baseline (speedup 1.0000x reference)
#include <cuda_runtime.h>

// Problem constants
#define Bq     8
#define Cq     128
#define HEADS  8
#define HC     16            // channels per head
#define Nq     16384         // H*W
#define NBH    (Bq*HEADS)    // 64

// Kernel-1 tiling
#define CHUNKS      8
#define CHUNK_COLS  (Nq/CHUNKS)   // 2048
#define TILE        128
#define NTILES      (CHUNK_COLS/TILE)  // 16
#define PAD         132           // row stride in smem (bank-shift of 4)

// Kernel-2 tiling: 4 columns per thread, 256 threads -> 1024 columns per block
#define COLS2       1024

// Scratch (no allocations allowed -> __device__ globals)
__device__ float g_pctx[NBH][CHUNKS][HC][HC];   // unnormalized partial context
__device__ float g_psum[NBH][CHUNKS][HC];       // partial row sums of exp(k)
__device__ float g_ctx [NBH][HC][HC];           // normalized context

// ---------------------------------------------------------------------------
// Kernel 1: per (b,h,chunk) compute partial  ctx'[r][c] = sum_n exp(k[r,n]) * v[c,n]
//           and partial row sums s[r] = sum_n exp(k[r,n]).
// 256 threads. Producer stages exp(k) and v tiles [16 x 128] into smem;
// consumer warps each own a 16-column strip and accumulate the full 16x16
// outer-product tile in registers (4 rows x 2 cols per lane).
// ---------------------------------------------------------------------------
__global__ __launch_bounds__(256)
void ctx_partial_kernel(const float* __restrict__ x1, const float* __restrict__ x2) {
    __shared__ float e_sm[HC][PAD];
    __shared__ float v_sm[HC][PAD];
    __shared__ float red_sm[8 * 256];   // per-warp ctx partials
    __shared__ float rs_sm[256];        // per-thread row sums

    const int tid   = threadIdx.x;
    const int chunk = blockIdx.x;
    const int h     = blockIdx.y;
    const int b     = blockIdx.z;
    const int bh    = b * HEADS + h;

    const int base  = (b * Cq + h * HC) * Nq + chunk * CHUNK_COLS;
    const float* kptr = x2 + base;   // keys/queries come from x2
    const float* vptr = x1 + base;   // values come from x1

    const int pr = tid >> 4;   // producer row (0..15)
    const int pl = tid & 15;   // producer lane within row
    const int w  = tid >> 5;   // warp id (0..7)
    const int l  = tid & 31;
    const int rg = l >> 3;     // row group: rows rg*4 .. rg*4+3
    const int cg = l & 7;      // col group: cols cg*2, cg*2+1

    float acc[4][2];
    #pragma unroll
    for (int a = 0; a < 4; a++) { acc[a][0] = 0.f; acc[a][1] = 0.f; }
    float rowsum = 0.f;

    for (int tile = 0; tile < NTILES; tile++) {
        const int tcol = tile * TILE;

        // ---- produce: exp(k) tile and v tile into smem ----
        #pragma unroll
        for (int i = 0; i < 2; i++) {
            const int t4 = pl + 16 * i;              // float4 index within row
            const int off = pr * Nq + tcol + 4 * t4;
            float4 kv = *(const float4*)(kptr + off);
            float4 e;
            e.x = __expf(kv.x); e.y = __expf(kv.y);
            e.z = __expf(kv.z); e.w = __expf(kv.w);
            rowsum += e.x + e.y + e.z + e.w;
            *(float4*)&e_sm[pr][4 * t4] = e;
            float4 vv = *(const float4*)(vptr + off);
            *(float4*)&v_sm[pr][4 * t4] = vv;
        }
        __syncthreads();

        // ---- consume: warp w covers columns [w*16, w*16+16) of the tile ----
        #pragma unroll
        for (int tb = 0; tb < 16; tb += 4) {
            const int t = w * 16 + tb;
            float4 er[4], vc[2];
            #pragma unroll
            for (int jr = 0; jr < 4; jr++)
                er[jr] = *(const float4*)&e_sm[rg * 4 + jr][t];
            #pragma unroll
            for (int jc = 0; jc < 2; jc++)
                vc[jc] = *(const float4*)&v_sm[cg * 2 + jc][t];
            #pragma unroll
            for (int jr = 0; jr < 4; jr++) {
                #pragma unroll
                for (int jc = 0; jc < 2; jc++) {
                    acc[jr][jc] += er[jr].x * vc[jc].x;
                    acc[jr][jc] += er[jr].y * vc[jc].y;
                    acc[jr][jc] += er[jr].z * vc[jc].z;
                    acc[jr][jc] += er[jr].w * vc[jc].w;
                }
            }
        }
        __syncthreads();
    }

    // ---- block epilogue: reduce 8 warp-tiles + row sums, write partials ----
    #pragma unroll
    for (int jr = 0; jr < 4; jr++)
        #pragma unroll
        for (int jc = 0; jc < 2; jc++)
            red_sm[w * 256 + (rg * 4 + jr) * 16 + (cg * 2 + jc)] = acc[jr][jc];
    rs_sm[tid] = rowsum;
    __syncthreads();

    float p = 0.f;
    #pragma unroll
    for (int ww = 0; ww < 8; ww++) p += red_sm[ww * 256 + tid];
    g_pctx[bh][chunk][tid >> 4][tid & 15] = p;

    if (tid < HC) {
        float s = 0.f;
        #pragma unroll
        for (int j = 0; j < 16; j++) s += rs_sm[tid * 16 + j];
        g_psum[bh][chunk][tid] = s;
    }
}

// ---------------------------------------------------------------------------
// Kernel 1.5: reduce chunk partials, normalize by row sums -> g_ctx
// ---------------------------------------------------------------------------
__global__ __launch_bounds__(256)
void ctx_reduce_kernel() {
    __shared__ float sinv[HC];
    const int bh  = blockIdx.x;
    const int tid = threadIdx.x;

    if (tid < HC) {
        float s = 0.f;
        #pragma unroll
        for (int c = 0; c < CHUNKS; c++) s += g_psum[bh][c][tid];
        sinv[tid] = 1.0f / s;
    }
    __syncthreads();

    const int r = tid >> 4, cc = tid & 15;
    float a = 0.f;
    #pragma unroll
    for (int c = 0; c < CHUNKS; c++) a += g_pctx[bh][c][r][cc];
    g_ctx[bh][r][cc] = a * sinv[r];
}

// ---------------------------------------------------------------------------
// Kernel 2: out[v][n] = (sum_k ctx[k][v] * exp(k[k,n])) / (sum_k exp(k[k,n]))
// Each thread handles 4 adjacent columns (float4 loads/stores, coalesced).
// exp values are consumed in the same k-loop that accumulates, so no e-array
// is ever materialized (keeps regs ~80, no spills, no launch-bounds cap).
// ---------------------------------------------------------------------------
__global__ __launch_bounds__(256)
void attend_kernel(const float* __restrict__ x2, float* __restrict__ out) {
    __shared__ float4 ctx4[HC][4];   // ctx[k][v] as 4 float4 per row k

    const int tid = threadIdx.x;
    const int h   = blockIdx.y;
    const int b   = blockIdx.z;
    const int bh  = b * HEADS + h;

    ((float*)ctx4)[tid] = ((const float*)g_ctx[bh])[tid];

    const int nn = blockIdx.x * COLS2 + 4 * tid;
    const float* kbase = x2  + (b * Cq + h * HC) * Nq + nn;
    float*       obase = out + (b * Cq + h * HC) * Nq + nn;
    __syncthreads();

    float4 acc[HC];
    #pragma unroll
    for (int v = 0; v < HC; v++) acc[v] = make_float4(0.f, 0.f, 0.f, 0.f);
    float4 s = make_float4(0.f, 0.f, 0.f, 0.f);

    #pragma unroll
    for (int k = 0; k < HC; k++) {
        float4 kv = *(const float4*)(kbase + k * Nq);
        float4 e;
        e.x = __expf(kv.x); e.y = __expf(kv.y);
        e.z = __expf(kv.z); e.w = __expf(kv.w);
        s.x += e.x; s.y += e.y; s.z += e.z; s.w += e.w;
        #pragma unroll
        for (int q = 0; q < 4; q++) {
            float4 c = ctx4[k][q];
            acc[q*4+0].x += e.x * c.x; acc[q*4+0].y += e.y * c.x;
            acc[q*4+0].z += e.z * c.x; acc[q*4+0].w += e.w * c.x;
            acc[q*4+1].x += e.x * c.y; acc[q*4+1].y += e.y * c.y;
            acc[q*4+1].z += e.z * c.y; acc[q*4+1].w += e.w * c.y;
            acc[q*4+2].x += e.x * c.z; acc[q*4+2].y += e.y * c.z;
            acc[q*4+2].z += e.z * c.z; acc[q*4+2].w += e.w * c.z;
            acc[q*4+3].x += e.x * c.w; acc[q*4+3].y += e.y * c.w;
            acc[q*4+3].z += e.z * c.w; acc[q*4+3].w += e.w * c.w;
        }
    }

    const float rx = 1.0f / s.x, ry = 1.0f / s.y;
    const float rz = 1.0f / s.z, rw = 1.0f / s.w;
    #pragma unroll
    for (int v = 0; v < HC; v++) {
        float4 o;
        o.x = acc[v].x * rx;
        o.y = acc[v].y * ry;
        o.z = acc[v].z * rz;
        o.w = acc[v].w * rw;
        *(float4*)(obase + v * Nq) = o;
    }
}

// ---------------------------------------------------------------------------
extern "C" void kernel_launch(void* const* d_in, const int* in_sizes, int n_in,
                              void* d_out, int out_size) {
    const float* x1 = (const float*)d_in[0];   // values
    const float* x2 = (const float*)d_in[1];   // keys / queries
    float* out = (float*)d_out;

    ctx_partial_kernel<<<dim3(CHUNKS, HEADS, Bq), 256>>>(x1, x2);
    ctx_reduce_kernel<<<NBH, 256>>>();
    attend_kernel<<<dim3(Nq / COLS2, HEADS, Bq), 256>>>(x2, out);
}

// round 5
// speedup vs baseline: 1.0375x; 1.0375x over previous
#include <cuda_runtime.h>

// Problem constants
#define Bq     8
#define Cq     128
#define HEADS  8
#define HC     16            // channels per head
#define Nq     16384         // H*W
#define NBH    (Bq*HEADS)    // 64

// Kernel-1 tiling
#define CHUNKS      8
#define CHUNK_COLS  (Nq/CHUNKS)   // 2048
#define TILE        128
#define NTILES      (CHUNK_COLS/TILE)  // 16
#define PAD         132           // row stride in smem (528B = 33*16 -> 16B-aligned rows)

// Kernel-2 tiling: 4 columns per thread, 256 threads -> 1024 columns per block
#define COLS2       1024

// Scratch (no allocations allowed -> __device__ globals)
__device__ float g_pctx[NBH][CHUNKS][HC][HC];   // unnormalized partial context
__device__ float g_psum[NBH][CHUNKS][HC];       // partial row sums of exp(k)
__device__ float g_ctx [NBH][HC][HC];           // normalized context

// ---- packed f32x2 helpers (Blackwell-native; ptxas never auto-fuses) ----
__device__ __forceinline__ unsigned long long fma2(unsigned long long a,
                                                   unsigned long long b,
                                                   unsigned long long c) {
    unsigned long long d;
    asm("fma.rn.f32x2 %0, %1, %2, %3;" : "=l"(d) : "l"(a), "l"(b), "l"(c));
    return d;
}
__device__ __forceinline__ unsigned long long add2(unsigned long long a,
                                                   unsigned long long b) {
    unsigned long long d;
    asm("add.rn.f32x2 %0, %1, %2;" : "=l"(d) : "l"(a), "l"(b));
    return d;
}
__device__ __forceinline__ unsigned long long pack2(float lo, float hi) {
    unsigned long long d;
    asm("mov.b64 %0, {%1, %2};" : "=l"(d) : "f"(lo), "f"(hi));
    return d;
}
__device__ __forceinline__ void unpack2(unsigned long long v, float& lo, float& hi) {
    asm("mov.b64 {%0, %1}, %2;" : "=f"(lo), "=f"(hi) : "l"(v));
}

// ---------------------------------------------------------------------------
// Kernel 1: per (b,h,chunk) partial  ctx'[r][c] = sum_n exp(k[r,n]) * v[c,n]
// Software-pipelined (double-buffered smem, ONE barrier per tile) with
// f32x2-packed accumulation along the reduction dimension.
// ---------------------------------------------------------------------------
__global__ __launch_bounds__(256)
void ctx_partial_kernel(const float* __restrict__ x1, const float* __restrict__ x2) {
    __shared__ float e_sm[2][HC][PAD];
    __shared__ float v_sm[2][HC][PAD];
    __shared__ float red_sm[8 * 256];   // per-warp ctx partials
    __shared__ float rs_sm[256];        // per-thread row sums

    const int tid   = threadIdx.x;
    const int chunk = blockIdx.x;
    const int h     = blockIdx.y;
    const int b     = blockIdx.z;
    const int bh    = b * HEADS + h;

    const int base  = (b * Cq + h * HC) * Nq + chunk * CHUNK_COLS;
    const float* kptr = x2 + base;   // keys/queries come from x2
    const float* vptr = x1 + base;   // values come from x1

    const int pr = tid >> 4;   // producer row (0..15)
    const int pl = tid & 15;   // producer lane within row
    const int w  = tid >> 5;   // warp id (0..7)
    const int l  = tid & 31;
    const int rg = l >> 3;     // row group: rows rg*4 .. rg*4+3
    const int cg = l & 7;      // col group: cols cg*2, cg*2+1

    unsigned long long accp[4][2];   // packed partial-pair accumulators
    #pragma unroll
    for (int a = 0; a < 4; a++) { accp[a][0] = 0ull; accp[a][1] = 0ull; }
    float rowsum = 0.f;

    const int t4a = pl;            // float4 index 0..15
    const int t4b = pl + 16;       // float4 index 16..31

    float4 kv0, kv1, vv0, vv1;     // staging registers for the in-flight tile

    // ---- prologue: load + stage tile 0 into buffer 0 ----
    {
        const int off = pr * Nq;
        kv0 = *(const float4*)(kptr + off + 4 * t4a);
        kv1 = *(const float4*)(kptr + off + 4 * t4b);
        vv0 = *(const float4*)(vptr + off + 4 * t4a);
        vv1 = *(const float4*)(vptr + off + 4 * t4b);
        float4 e0, e1;
        e0.x = __expf(kv0.x); e0.y = __expf(kv0.y); e0.z = __expf(kv0.z); e0.w = __expf(kv0.w);
        e1.x = __expf(kv1.x); e1.y = __expf(kv1.y); e1.z = __expf(kv1.z); e1.w = __expf(kv1.w);
        rowsum += e0.x + e0.y + e0.z + e0.w + e1.x + e1.y + e1.z + e1.w;
        *(float4*)&e_sm[0][pr][4 * t4a] = e0;
        *(float4*)&e_sm[0][pr][4 * t4b] = e1;
        *(float4*)&v_sm[0][pr][4 * t4a] = vv0;
        *(float4*)&v_sm[0][pr][4 * t4b] = vv1;
    }
    __syncthreads();

    for (int tile = 0; tile < NTILES; tile++) {
        const int cur = tile & 1;
        const int nxt = cur ^ 1;

        // ---- issue loads for tile+1 (latency hidden by consume below) ----
        if (tile + 1 < NTILES) {
            const int off = pr * Nq + (tile + 1) * TILE;
            kv0 = *(const float4*)(kptr + off + 4 * t4a);
            kv1 = *(const float4*)(kptr + off + 4 * t4b);
            vv0 = *(const float4*)(vptr + off + 4 * t4a);
            vv1 = *(const float4*)(vptr + off + 4 * t4b);
        }

        // ---- consume tile from smem buffer `cur` (f32x2-packed FMAs) ----
        #pragma unroll
        for (int tb = 0; tb < 16; tb += 4) {
            const int t = w * 16 + tb;   // t*4 bytes is 16B-aligned (t % 4 == 0)
            ulonglong2 er2[4], vc2[2];
            #pragma unroll
            for (int jr = 0; jr < 4; jr++)
                er2[jr] = *(const ulonglong2*)&e_sm[cur][rg * 4 + jr][t];
            #pragma unroll
            for (int jc = 0; jc < 2; jc++)
                vc2[jc] = *(const ulonglong2*)&v_sm[cur][cg * 2 + jc][t];
            #pragma unroll
            for (int jr = 0; jr < 4; jr++) {
                #pragma unroll
                for (int jc = 0; jc < 2; jc++) {
                    accp[jr][jc] = fma2(er2[jr].x, vc2[jc].x, accp[jr][jc]);
                    accp[jr][jc] = fma2(er2[jr].y, vc2[jc].y, accp[jr][jc]);
                }
            }
        }

        // ---- stage tile+1 into buffer `nxt` (safe: last read fenced at t-1) ----
        if (tile + 1 < NTILES) {
            float4 e0, e1;
            e0.x = __expf(kv0.x); e0.y = __expf(kv0.y); e0.z = __expf(kv0.z); e0.w = __expf(kv0.w);
            e1.x = __expf(kv1.x); e1.y = __expf(kv1.y); e1.z = __expf(kv1.z); e1.w = __expf(kv1.w);
            rowsum += e0.x + e0.y + e0.z + e0.w + e1.x + e1.y + e1.z + e1.w;
            *(float4*)&e_sm[nxt][pr][4 * t4a] = e0;
            *(float4*)&e_sm[nxt][pr][4 * t4b] = e1;
            *(float4*)&v_sm[nxt][pr][4 * t4a] = vv0;
            *(float4*)&v_sm[nxt][pr][4 * t4b] = vv1;
        }
        __syncthreads();
    }

    // ---- block epilogue: horizontal add, reduce 8 warp-tiles, write partials ----
    #pragma unroll
    for (int jr = 0; jr < 4; jr++)
        #pragma unroll
        for (int jc = 0; jc < 2; jc++) {
            float lo, hi;
            unpack2(accp[jr][jc], lo, hi);
            red_sm[w * 256 + (rg * 4 + jr) * 16 + (cg * 2 + jc)] = lo + hi;
        }
    rs_sm[tid] = rowsum;
    __syncthreads();

    float p = 0.f;
    #pragma unroll
    for (int ww = 0; ww < 8; ww++) p += red_sm[ww * 256 + tid];
    g_pctx[bh][chunk][tid >> 4][tid & 15] = p;

    if (tid < HC) {
        float s = 0.f;
        #pragma unroll
        for (int j = 0; j < 16; j++) s += rs_sm[tid * 16 + j];
        g_psum[bh][chunk][tid] = s;
    }
}

// ---------------------------------------------------------------------------
// Kernel 1.5: reduce chunk partials, normalize by row sums -> g_ctx
// ---------------------------------------------------------------------------
__global__ __launch_bounds__(256)
void ctx_reduce_kernel() {
    __shared__ float sinv[HC];
    const int bh  = blockIdx.x;
    const int tid = threadIdx.x;

    if (tid < HC) {
        float s = 0.f;
        #pragma unroll
        for (int c = 0; c < CHUNKS; c++) s += g_psum[bh][c][tid];
        sinv[tid] = 1.0f / s;
    }
    __syncthreads();

    const int r = tid >> 4, cc = tid & 15;
    float a = 0.f;
    #pragma unroll
    for (int c = 0; c < CHUNKS; c++) a += g_pctx[bh][c][r][cc];
    g_ctx[bh][r][cc] = a * sinv[r];
}

// ---------------------------------------------------------------------------
// Kernel 2: out[v][n] = (sum_k ctx[k][v] * exp(k[k,n])) / (sum_k exp(k[k,n]))
// 4 adjacent columns per thread. ctx pre-duplicated in smem as float2{c,c}
// so the inner loop is pure FFMA2 (no dup movs): acc packed over columns.
// ---------------------------------------------------------------------------
__global__ __launch_bounds__(256)
void attend_kernel(const float* __restrict__ x2, float* __restrict__ out) {
    __shared__ float2 cdup[HC][HC];   // cdup[k][v] = {ctx[k][v], ctx[k][v]}

    const int tid = threadIdx.x;
    const int h   = blockIdx.y;
    const int b   = blockIdx.z;
    const int bh  = b * HEADS + h;

    {
        const int k = tid >> 4, v = tid & 15;
        const float c = g_ctx[bh][k][v];
        cdup[k][v] = make_float2(c, c);
    }

    const int nn = blockIdx.x * COLS2 + 4 * tid;
    const float* kbase = x2  + (b * Cq + h * HC) * Nq + nn;
    float*       obase = out + (b * Cq + h * HC) * Nq + nn;
    __syncthreads();

    unsigned long long acc01[HC], acc23[HC];
    #pragma unroll
    for (int v = 0; v < HC; v++) { acc01[v] = 0ull; acc23[v] = 0ull; }
    unsigned long long s01 = 0ull, s23 = 0ull;

    #pragma unroll
    for (int k = 0; k < HC; k++) {
        float4 kv = *(const float4*)(kbase + k * Nq);
        const unsigned long long e01 = pack2(__expf(kv.x), __expf(kv.y));
        const unsigned long long e23 = pack2(__expf(kv.z), __expf(kv.w));
        s01 = add2(s01, e01);
        s23 = add2(s23, e23);
        #pragma unroll
        for (int v = 0; v < HC; v += 2) {
            // cdup[k][v] at byte offset (k*16+v)*8, v even -> 16B-aligned
            ulonglong2 c2 = *(const ulonglong2*)&cdup[k][v];
            acc01[v]     = fma2(e01, c2.x, acc01[v]);
            acc23[v]     = fma2(e23, c2.x, acc23[v]);
            acc01[v + 1] = fma2(e01, c2.y, acc01[v + 1]);
            acc23[v + 1] = fma2(e23, c2.y, acc23[v + 1]);
        }
    }

    float sx, sy, sz, sw;
    unpack2(s01, sx, sy);
    unpack2(s23, sz, sw);
    const float rx = 1.0f / sx, ry = 1.0f / sy;
    const float rz = 1.0f / sz, rw = 1.0f / sw;

    #pragma unroll
    for (int v = 0; v < HC; v++) {
        float ax, ay, az, aw;
        unpack2(acc01[v], ax, ay);
        unpack2(acc23[v], az, aw);
        float4 o;
        o.x = ax * rx;
        o.y = ay * ry;
        o.z = az * rz;
        o.w = aw * rw;
        *(float4*)(obase + v * Nq) = o;
    }
}

// ---------------------------------------------------------------------------
extern "C" void kernel_launch(void* const* d_in, const int* in_sizes, int n_in,
                              void* d_out, int out_size) {
    const float* x1 = (const float*)d_in[0];   // values
    const float* x2 = (const float*)d_in[1];   // keys / queries
    float* out = (float*)d_out;

    ctx_partial_kernel<<<dim3(CHUNKS, HEADS, Bq), 256>>>(x1, x2);
    ctx_reduce_kernel<<<NBH, 256>>>();
    attend_kernel<<<dim3(Nq / COLS2, HEADS, Bq), 256>>>(x2, out);
}